// round 13
// baseline (speedup 1.0000x reference)
#include <cuda_runtime.h>
#include <cuda_bf16.h>
#include <math.h>
#include <stdint.h>

#define LSEQ   4096
#define HIDDEN 4096
#define NH     32
#define NKV    8
#define HD     128
#define CHUNKS 128
#define NC     32
#define QDIM   4096   // NH*HD
#define KVDIM  1024   // NKV*HD

// single dynamic smem declaration for ALL kernels
extern __shared__ __align__(1024) unsigned char dyn_smem[];

// ---------------- scratch (static device globals; no allocation) ----------------
__device__ float g_q[(size_t)LSEQ * QDIM];
__device__ float g_k[(size_t)LSEQ * KVDIM];
__device__ float g_v[(size_t)LSEQ * KVDIM];
__device__ float g_gate[(size_t)LSEQ * QDIM];
__device__ float g_y[(size_t)LSEQ * QDIM];
__device__ float g_dt[LSEQ * NH];
__device__ float g_G[LSEQ * NH];
__device__ float g_cdec[NC * NH];
__device__ float g_cs[(size_t)NC * NH * HD * HD];
__device__ float g_prev[(size_t)NC * NH * HD * HD];

__device__ __forceinline__ unsigned pack_bf2(float a, float b) {
    __nv_bfloat162 t = __floats2bfloat162_rn(a, b);
    return reinterpret_cast<unsigned&>(t);
}

// ---------------- GEMM tile body (round-10 winner): 128x256 CTA / 512 thr / 64x32 warp --
__device__ __forceinline__ void gemm_tile(const float* __restrict__ A,
                                          const float* __restrict__ B,
                                          float* __restrict__ C,
                                          int N, int K, int bm, int bn) {
    unsigned* smem_u = (unsigned*)dyn_smem;
    const int tid = threadIdx.x;
    const int warp = tid >> 5, lane = tid & 31;
    const int wm = warp >> 3, wn = warp & 7;   // 2 x 8 warps, warp tile 64x32

    float acc[4][4][4];
#pragma unroll
    for (int a = 0; a < 4; a++)
#pragma unroll
        for (int b = 0; b < 4; b++)
#pragma unroll
            for (int c = 0; c < 4; c++) acc[a][b][c] = 0.f;

    const int c4 = tid & 7;
    const int k0 = c4 * 4;
    const int ks0 = c4 >> 2;
    const int ki = (c4 & 3) * 4;
    const int row0 = tid >> 3;            // 0..63

    const float* a_base = A + (size_t)(bm + row0) * K + k0;
    const float* b_base = B + (size_t)(bn + row0) * K + k0;
    const size_t gstride = (size_t)64 * K;

    const int riA = row0 & 15, tmA = row0 >> 4;
    const int laneA = (riA & 7) * 4 + ((ki & 7) >> 1);
    const int regA = (riA >> 3) + ((ki >> 3) << 1);
    const int a_st0 = ((ks0 * 8 + tmA) * 32 + laneA) * 4 + regA;
    const int tnB = row0 >> 3, ciB = row0 & 7;
    const int laneB = ciB * 4 + ((ki & 7) >> 1);
    const int regB = ki >> 3;
    const int b_st0 = ((ks0 * 32 + tnB) * 32 + laneB) * 2 + regB;

    float4 ar[2], br[4];
#pragma unroll
    for (int i = 0; i < 2; i++) ar[i] = *(const float4*)(a_base + i * gstride);
#pragma unroll
    for (int i = 0; i < 4; i++) br[i] = *(const float4*)(b_base + i * gstride);

    auto store_tiles = [&](unsigned* base) {
        unsigned* Ah = base;
        unsigned* Al = base + 2048;
        unsigned* Bh = base + 4096;
        unsigned* Bl = base + 8192;
#pragma unroll
        for (int i = 0; i < 2; i++) {
            float4 v = ar[i];
            __nv_bfloat162 h01 = __floats2bfloat162_rn(v.x, v.y);
            __nv_bfloat162 h23 = __floats2bfloat162_rn(v.z, v.w);
            float2 f01 = __bfloat1622float2(h01);
            float2 f23 = __bfloat1622float2(h23);
            const int st = a_st0 + i * 512;
            Ah[st]     = reinterpret_cast<unsigned&>(h01);
            Ah[st + 4] = reinterpret_cast<unsigned&>(h23);
            Al[st]     = pack_bf2(v.x - f01.x, v.y - f01.y);
            Al[st + 4] = pack_bf2(v.z - f23.x, v.w - f23.y);
        }
#pragma unroll
        for (int i = 0; i < 4; i++) {
            float4 v = br[i];
            __nv_bfloat162 h01 = __floats2bfloat162_rn(v.x, v.y);
            __nv_bfloat162 h23 = __floats2bfloat162_rn(v.z, v.w);
            float2 f01 = __bfloat1622float2(h01);
            float2 f23 = __bfloat1622float2(h23);
            const int st = b_st0 + i * 512;
            Bh[st]     = reinterpret_cast<unsigned&>(h01);
            Bh[st + 2] = reinterpret_cast<unsigned&>(h23);
            Bl[st]     = pack_bf2(v.x - f01.x, v.y - f01.y);
            Bl[st + 2] = pack_bf2(v.z - f23.x, v.w - f23.y);
        }
    };

    store_tiles(smem_u);
    __syncthreads();

    const int nk = K >> 5;
    for (int kb = 0; kb < nk; kb++) {
        const int cur = kb & 1;
        const bool has_next = (kb + 1) < nk;
        if (has_next) {
            const int off = (kb + 1) * 32;
#pragma unroll
            for (int i = 0; i < 2; i++) ar[i] = *(const float4*)(a_base + i * gstride + off);
#pragma unroll
            for (int i = 0; i < 4; i++) br[i] = *(const float4*)(b_base + i * gstride + off);
        }
        const unsigned* base = smem_u + cur * 12288;
        const unsigned* Ahb = base;
        const unsigned* Alb = base + 2048;
        const unsigned* Bhb = base + 4096;
        const unsigned* Blb = base + 8192;
#pragma unroll
        for (int ks = 0; ks < 2; ks++) {
            unsigned bh[4][2], bl[4][2];
#pragma unroll
            for (int nt = 0; nt < 4; nt++) {
                const int tn = wn * 4 + nt;
                uint2 vh = *(const uint2*)(Bhb + ((ks * 32 + tn) * 32 + lane) * 2);
                uint2 vl = *(const uint2*)(Blb + ((ks * 32 + tn) * 32 + lane) * 2);
                bh[nt][0] = vh.x; bh[nt][1] = vh.y;
                bl[nt][0] = vl.x; bl[nt][1] = vl.y;
            }
#pragma unroll
            for (int mt = 0; mt < 4; mt++) {
                const int tm = wm * 4 + mt;
                uint4 avh = *(const uint4*)(Ahb + ((ks * 8 + tm) * 32 + lane) * 4);
                uint4 avl = *(const uint4*)(Alb + ((ks * 8 + tm) * 32 + lane) * 4);
#pragma unroll
                for (int nt = 0; nt < 4; nt++) {
                    asm volatile(
                        "mma.sync.aligned.m16n8k16.row.col.f32.bf16.bf16.f32 "
                        "{%0,%1,%2,%3}, {%4,%5,%6,%7}, {%8,%9}, {%0,%1,%2,%3};"
                        : "+f"(acc[mt][nt][0]), "+f"(acc[mt][nt][1]),
                          "+f"(acc[mt][nt][2]), "+f"(acc[mt][nt][3])
                        : "r"(avh.x), "r"(avh.y), "r"(avh.z), "r"(avh.w),
                          "r"(bh[nt][0]), "r"(bh[nt][1]));
                    asm volatile(
                        "mma.sync.aligned.m16n8k16.row.col.f32.bf16.bf16.f32 "
                        "{%0,%1,%2,%3}, {%4,%5,%6,%7}, {%8,%9}, {%0,%1,%2,%3};"
                        : "+f"(acc[mt][nt][0]), "+f"(acc[mt][nt][1]),
                          "+f"(acc[mt][nt][2]), "+f"(acc[mt][nt][3])
                        : "r"(avh.x), "r"(avh.y), "r"(avh.z), "r"(avh.w),
                          "r"(bl[nt][0]), "r"(bl[nt][1]));
                    asm volatile(
                        "mma.sync.aligned.m16n8k16.row.col.f32.bf16.bf16.f32 "
                        "{%0,%1,%2,%3}, {%4,%5,%6,%7}, {%8,%9}, {%0,%1,%2,%3};"
                        : "+f"(acc[mt][nt][0]), "+f"(acc[mt][nt][1]),
                          "+f"(acc[mt][nt][2]), "+f"(acc[mt][nt][3])
                        : "r"(avl.x), "r"(avl.y), "r"(avl.z), "r"(avl.w),
                          "r"(bh[nt][0]), "r"(bh[nt][1]));
                }
            }
        }
        if (has_next) {
            store_tiles(smem_u + ((kb + 1) & 1) * 12288);
            __syncthreads();
        }
    }

#pragma unroll
    for (int mt = 0; mt < 4; mt++) {
        const int row0e = bm + wm * 64 + mt * 16 + (lane >> 2);
#pragma unroll
        for (int nt = 0; nt < 4; nt++) {
            const int col = bn + wn * 32 + nt * 8 + (lane & 3) * 2;
            *(float2*)(C + (size_t)row0e * N + col) = make_float2(acc[mt][nt][0], acc[mt][nt][1]);
            *(float2*)(C + (size_t)(row0e + 8) * N + col) = make_float2(acc[mt][nt][2], acc[mt][nt][3]);
        }
    }
}

// generic single-matrix GEMM (output projection)
__global__ void __launch_bounds__(512, 1) gemm_big(const float* __restrict__ A,
                                                   const float* __restrict__ B,
                                                   float* __restrict__ C,
                                                   int M, int N, int K) {
    gemm_tile(A, B, C, N, K, blockIdx.y * 128, blockIdx.x * 256);
}

// fused Q/K/V/G projection: x-tile index picks matrix.
// layout: [0,16) Q | [16,20) K | [20,24) V | [24,40) G
__global__ void __launch_bounds__(512, 1) gemm_qkvg(const float* __restrict__ hs,
                                                    const float* __restrict__ Wq,
                                                    const float* __restrict__ Wk,
                                                    const float* __restrict__ Wv,
                                                    const float* __restrict__ Wg,
                                                    float* __restrict__ q,
                                                    float* __restrict__ k,
                                                    float* __restrict__ v,
                                                    float* __restrict__ gate) {
    const int bx = blockIdx.x;
    const float* B;
    float* C;
    int N, bn;
    if (bx < 16)      { B = Wq; C = q;    N = QDIM;  bn = bx * 256; }
    else if (bx < 20) { B = Wk; C = k;    N = KVDIM; bn = (bx - 16) * 256; }
    else if (bx < 24) { B = Wv; C = v;    N = KVDIM; bn = (bx - 20) * 256; }
    else              { B = Wg; C = gate; N = QDIM;  bn = (bx - 24) * 256; }
    gemm_tile(hs, B, C, N, HIDDEN, blockIdx.y * 128, bn);
}

// ---------------- dt = softplus(hs @ Win^T + dt_bias) ----------------
__global__ void dt_kernel(const float* __restrict__ hs, const float* __restrict__ Win,
                          const float* __restrict__ dtb) {
    __shared__ float srow[HIDDEN];
    __shared__ float red[256];
    const int l = blockIdx.x;
    for (int k = threadIdx.x; k < HIDDEN; k += 256) srow[k] = hs[(size_t)l * HIDDEN + k];
    __syncthreads();
    const int h = threadIdx.x & 31;
    const int part = threadIdx.x >> 5;
    const float* w = Win + (size_t)h * HIDDEN + part * 512;
    const float* s = srow + part * 512;
    float acc = 0.f;
#pragma unroll 4
    for (int k = 0; k < 512; k++) acc += s[k] * w[k];
    red[threadIdx.x] = acc;
    __syncthreads();
    if (threadIdx.x < 32) {
        float t = 0.f;
#pragma unroll
        for (int p = 0; p < 8; p++) t += red[p * 32 + h];
        t += dtb[h];
        float sp = fmaxf(t, 0.f) + log1pf(expf(-fabsf(t)));
        g_dt[l * NH + h] = sp;
    }
}

// ---------------- per-(chunk,head) inclusive cumsum of g = dt*A ----------------
__global__ void scan_kernel(const float* __restrict__ A_log) {
    const int hc = blockIdx.x;
    const int h = hc & (NH - 1);
    const int c = hc >> 5;
    const float A = -expf(A_log[h]);
    const int lane = threadIdx.x;
    float carry = 0.f;
    for (int s0 = 0; s0 < CHUNKS; s0 += 32) {
        const int l = c * CHUNKS + s0 + lane;
        float val = g_dt[l * NH + h] * A;
#pragma unroll
        for (int off = 1; off < 32; off <<= 1) {
            float n = __shfl_up_sync(0xffffffffu, val, off);
            if (lane >= off) val += n;
        }
        val += carry;
        g_G[l * NH + h] = val;
        carry = __shfl_sync(0xffffffffu, val, 31);
    }
    if (lane == 31) g_cdec[c * NH + h] = expf(carry);
}

// ---------------- RoPE in place ----------------
__global__ void rope_kernel(float* __restrict__ x, int nheads) {
    const long idx = (long)blockIdx.x * blockDim.x + threadIdx.x;
    const long total = (long)LSEQ * nheads * 64;
    if (idx >= total) return;
    const int d = (int)(idx & 63);
    const int h = (int)((idx >> 6) % nheads);
    const long l = idx / ((long)64 * nheads);
    const float inv = powf(10000.0f, -(2.0f * d) / 128.0f);
    const float ang = (float)l * inv;
    float cs, sn;
    __sincosf(ang, &sn, &cs);
    float* base = x + l * (size_t)(nheads * HD) + (size_t)h * HD;
    const float x1 = base[d];
    const float x2 = base[d + 64];
    base[d]      = x1 * cs - x2 * sn;
    base[d + 64] = x2 * cs + x1 * sn;
}

// ---------------- intra-chunk: scores, decay mask, y_intra, cstates (round-10/3 FFMA) ---
__global__ void __launch_bounds__(256) intra_kernel() {
    float* smem = (float*)dyn_smem;
    float* sP = smem;                 // 128*129, P^T (stored [j][i])
    float* sA = sP + 128 * 129;       // 16*128
    float* sB = sA + 16 * 128;        // 16*128
    __shared__ float sG[128];
    __shared__ float sDt[128];

    const int c = blockIdx.x, h = blockIdx.y;
    const int kvh = h >> 2;
    const int tid = threadIdx.x;
    const int tr = tid >> 4, tc = tid & 15;
    const float* qp = g_q + (size_t)(c * CHUNKS) * QDIM + (size_t)h * HD;
    const float* kp = g_k + (size_t)(c * CHUNKS) * KVDIM + (size_t)kvh * HD;
    const float* vp = g_v + (size_t)(c * CHUNKS) * KVDIM + (size_t)kvh * HD;

    if (tid < 128) {
        sG[tid] = g_G[(c * CHUNKS + tid) * NH + h];
        sDt[tid] = g_dt[(c * CHUNKS + tid) * NH + h];
    }
    __syncthreads();
    const float Glast = sG[127];

    float acc[8][8];
#pragma unroll
    for (int i = 0; i < 8; i++)
#pragma unroll
        for (int j = 0; j < 8; j++) acc[i][j] = 0.f;

    const int rowA = tid >> 1;
    const int kk0 = (tid & 1) * 8;
    for (int d0 = 0; d0 < HD; d0 += 16) {
        const float* ap = qp + (size_t)rowA * QDIM + d0 + kk0;
        float4 a0 = *(const float4*)ap;
        float4 a1 = *(const float4*)(ap + 4);
        sA[(kk0 + 0) * 128 + rowA] = a0.x;
        sA[(kk0 + 1) * 128 + rowA] = a0.y;
        sA[(kk0 + 2) * 128 + rowA] = a0.z;
        sA[(kk0 + 3) * 128 + rowA] = a0.w;
        sA[(kk0 + 4) * 128 + rowA] = a1.x;
        sA[(kk0 + 5) * 128 + rowA] = a1.y;
        sA[(kk0 + 6) * 128 + rowA] = a1.z;
        sA[(kk0 + 7) * 128 + rowA] = a1.w;
        const float* bp = kp + (size_t)rowA * KVDIM + d0 + kk0;
        float4 b0 = *(const float4*)bp;
        float4 b1 = *(const float4*)(bp + 4);
        sB[(kk0 + 0) * 128 + rowA] = b0.x;
        sB[(kk0 + 1) * 128 + rowA] = b0.y;
        sB[(kk0 + 2) * 128 + rowA] = b0.z;
        sB[(kk0 + 3) * 128 + rowA] = b0.w;
        sB[(kk0 + 4) * 128 + rowA] = b1.x;
        sB[(kk0 + 5) * 128 + rowA] = b1.y;
        sB[(kk0 + 6) * 128 + rowA] = b1.z;
        sB[(kk0 + 7) * 128 + rowA] = b1.w;
        __syncthreads();
#pragma unroll
        for (int kk = 0; kk < 16; kk++) {
            float av[8], bv[8];
#pragma unroll
            for (int i = 0; i < 8; i++) av[i] = sA[kk * 128 + tr * 8 + i];
#pragma unroll
            for (int j = 0; j < 8; j++) bv[j] = sB[kk * 128 + tc * 8 + j];
#pragma unroll
            for (int i = 0; i < 8; i++)
#pragma unroll
                for (int j = 0; j < 8; j++) acc[i][j] += av[i] * bv[j];
        }
        __syncthreads();
    }

#pragma unroll
    for (int ii = 0; ii < 8; ii++) {
        const int i = tr * 8 + ii;
        const float Gi = sG[i];
#pragma unroll
        for (int jj = 0; jj < 8; jj++) {
            const int j = tc * 8 + jj;
            const float p = (i >= j) ? acc[ii][jj] * expf(Gi - sG[j]) : 0.f;
            sP[j * 129 + i] = p;
        }
    }
    __syncthreads();

#pragma unroll
    for (int i = 0; i < 8; i++)
#pragma unroll
        for (int j = 0; j < 8; j++) acc[i][j] = 0.f;
    {
        const int kkl = tid >> 4;
        const int e0 = (tid & 15) * 8;
        for (int j0 = 0; j0 < 128; j0 += 16) {
            const float dtv = sDt[j0 + kkl];
            const float* xp = vp + (size_t)(j0 + kkl) * KVDIM + e0;
            float4 x0 = *(const float4*)xp;
            float4 x1 = *(const float4*)(xp + 4);
            sB[kkl * 128 + e0 + 0] = x0.x * dtv;
            sB[kkl * 128 + e0 + 1] = x0.y * dtv;
            sB[kkl * 128 + e0 + 2] = x0.z * dtv;
            sB[kkl * 128 + e0 + 3] = x0.w * dtv;
            sB[kkl * 128 + e0 + 4] = x1.x * dtv;
            sB[kkl * 128 + e0 + 5] = x1.y * dtv;
            sB[kkl * 128 + e0 + 6] = x1.z * dtv;
            sB[kkl * 128 + e0 + 7] = x1.w * dtv;
            __syncthreads();
#pragma unroll
            for (int kk = 0; kk < 16; kk++) {
                float av[8], bv[8];
#pragma unroll
                for (int i = 0; i < 8; i++) av[i] = sP[(j0 + kk) * 129 + tr * 8 + i];
#pragma unroll
                for (int j = 0; j < 8; j++) bv[j] = sB[kk * 128 + tc * 8 + j];
#pragma unroll
                for (int i = 0; i < 8; i++)
#pragma unroll
                    for (int j = 0; j < 8; j++) acc[i][j] += av[i] * bv[j];
            }
            __syncthreads();
        }
    }
#pragma unroll
    for (int ii = 0; ii < 8; ii++) {
        float* yp = g_y + (size_t)(c * CHUNKS + tr * 8 + ii) * QDIM + (size_t)h * HD + tc * 8;
        *(float4*)yp = make_float4(acc[ii][0], acc[ii][1], acc[ii][2], acc[ii][3]);
        *(float4*)(yp + 4) = make_float4(acc[ii][4], acc[ii][5], acc[ii][6], acc[ii][7]);
    }

#pragma unroll
    for (int i = 0; i < 8; i++)
#pragma unroll
        for (int j = 0; j < 8; j++) acc[i][j] = 0.f;
    {
        const int kkl = tid >> 4;
        const int e0 = (tid & 15) * 8;
        for (int j0 = 0; j0 < 128; j0 += 16) {
            const float w = expf(Glast - sG[j0 + kkl]);
            const float dtv = sDt[j0 + kkl];
            const float* kp2 = kp + (size_t)(j0 + kkl) * KVDIM + e0;
            const float* xp = vp + (size_t)(j0 + kkl) * KVDIM + e0;
            float4 k0v = *(const float4*)kp2;
            float4 k1v = *(const float4*)(kp2 + 4);
            float4 x0 = *(const float4*)xp;
            float4 x1 = *(const float4*)(xp + 4);
            sA[kkl * 128 + e0 + 0] = k0v.x * w;
            sA[kkl * 128 + e0 + 1] = k0v.y * w;
            sA[kkl * 128 + e0 + 2] = k0v.z * w;
            sA[kkl * 128 + e0 + 3] = k0v.w * w;
            sA[kkl * 128 + e0 + 4] = k1v.x * w;
            sA[kkl * 128 + e0 + 5] = k1v.y * w;
            sA[kkl * 128 + e0 + 6] = k1v.z * w;
            sA[kkl * 128 + e0 + 7] = k1v.w * w;
            sB[kkl * 128 + e0 + 0] = x0.x * dtv;
            sB[kkl * 128 + e0 + 1] = x0.y * dtv;
            sB[kkl * 128 + e0 + 2] = x0.z * dtv;
            sB[kkl * 128 + e0 + 3] = x0.w * dtv;
            sB[kkl * 128 + e0 + 4] = x1.x * dtv;
            sB[kkl * 128 + e0 + 5] = x1.y * dtv;
            sB[kkl * 128 + e0 + 6] = x1.z * dtv;
            sB[kkl * 128 + e0 + 7] = x1.w * dtv;
            __syncthreads();
#pragma unroll
            for (int kk = 0; kk < 16; kk++) {
                float av[8], bv[8];
#pragma unroll
                for (int i = 0; i < 8; i++) av[i] = sA[kk * 128 + tr * 8 + i];
#pragma unroll
                for (int j = 0; j < 8; j++) bv[j] = sB[kk * 128 + tc * 8 + j];
#pragma unroll
                for (int i = 0; i < 8; i++)
#pragma unroll
                    for (int j = 0; j < 8; j++) acc[i][j] += av[i] * bv[j];
            }
            __syncthreads();
        }
    }
    float* csp = g_cs + (size_t)(c * NH + h) * HD * HD;
#pragma unroll
    for (int ii = 0; ii < 8; ii++) {
        float* cp = csp + (size_t)(tr * 8 + ii) * HD + tc * 8;
        *(float4*)cp = make_float4(acc[ii][0], acc[ii][1], acc[ii][2], acc[ii][3]);
        *(float4*)(cp + 4) = make_float4(acc[ii][4], acc[ii][5], acc[ii][6], acc[ii][7]);
    }
}

// ---------------- sequential chunk recurrence ----------------
__global__ void recur_kernel() {
    const int idx = blockIdx.x * blockDim.x + threadIdx.x;
    if (idx >= NH * HD * HD) return;
    const int h = idx / (HD * HD);
    const int de = idx % (HD * HD);
    float state = 0.f;
#pragma unroll 1
    for (int c = 0; c < NC; c++) {
        const size_t off = (size_t)(c * NH + h) * HD * HD + de;
        g_prev[off] = state;
        state = state * g_cdec[c * NH + h] + g_cs[off];
    }
}

// ---------------- inter-chunk + combine + RMSNorm + SiLU gate (round-10/3 FFMA) --------
__global__ void __launch_bounds__(256) inter_kernel(const float* __restrict__ gnorm) {
    float* smem = (float*)dyn_smem;
    float* sY = smem;               // 128*129
    float* sA = sY + 128 * 129;     // 16*128
    float* sB = sA + 16 * 128;      // 16*128
    __shared__ float sG[128];
    __shared__ float sScale[128];
    __shared__ float sGn[128];

    const int c = blockIdx.x, h = blockIdx.y;
    const int tid = threadIdx.x;
    const int tr = tid >> 4, tc = tid & 15;
    const float* qp = g_q + (size_t)(c * CHUNKS) * QDIM + (size_t)h * HD;
    const float* pp = g_prev + (size_t)(c * NH + h) * HD * HD;

    if (tid < 128) {
        sG[tid] = g_G[(c * CHUNKS + tid) * NH + h];
        sGn[tid] = gnorm[tid];
    }
    __syncthreads();

    float acc[8][8];
#pragma unroll
    for (int i = 0; i < 8; i++)
#pragma unroll
        for (int j = 0; j < 8; j++) acc[i][j] = 0.f;

    const int rowA = tid >> 1;
    const int kk0 = (tid & 1) * 8;
    const int kkl = tid >> 4;
    const int e0 = (tid & 15) * 8;
    for (int d0 = 0; d0 < HD; d0 += 16) {
        const float eg = expf(sG[rowA]);
        const float* ap = qp + (size_t)rowA * QDIM + d0 + kk0;
        float4 a0 = *(const float4*)ap;
        float4 a1 = *(const float4*)(ap + 4);
        sA[(kk0 + 0) * 128 + rowA] = a0.x * eg;
        sA[(kk0 + 1) * 128 + rowA] = a0.y * eg;
        sA[(kk0 + 2) * 128 + rowA] = a0.z * eg;
        sA[(kk0 + 3) * 128 + rowA] = a0.w * eg;
        sA[(kk0 + 4) * 128 + rowA] = a1.x * eg;
        sA[(kk0 + 5) * 128 + rowA] = a1.y * eg;
        sA[(kk0 + 6) * 128 + rowA] = a1.z * eg;
        sA[(kk0 + 7) * 128 + rowA] = a1.w * eg;
        const float* bp = pp + (size_t)(d0 + kkl) * HD + e0;
        float4 b0 = *(const float4*)bp;
        float4 b1 = *(const float4*)(bp + 4);
        sB[kkl * 128 + e0 + 0] = b0.x;
        sB[kkl * 128 + e0 + 1] = b0.y;
        sB[kkl * 128 + e0 + 2] = b0.z;
        sB[kkl * 128 + e0 + 3] = b0.w;
        sB[kkl * 128 + e0 + 4] = b1.x;
        sB[kkl * 128 + e0 + 5] = b1.y;
        sB[kkl * 128 + e0 + 6] = b1.z;
        sB[kkl * 128 + e0 + 7] = b1.w;
        __syncthreads();
#pragma unroll
        for (int kk = 0; kk < 16; kk++) {
            float av[8], bv[8];
#pragma unroll
            for (int i = 0; i < 8; i++) av[i] = sA[kk * 128 + tr * 8 + i];
#pragma unroll
            for (int j = 0; j < 8; j++) bv[j] = sB[kk * 128 + tc * 8 + j];
#pragma unroll
            for (int i = 0; i < 8; i++)
#pragma unroll
                for (int j = 0; j < 8; j++) acc[i][j] += av[i] * bv[j];
        }
        __syncthreads();
    }

#pragma unroll
    for (int ii = 0; ii < 8; ii++) {
        const int i = tr * 8 + ii;
        const float* yin = g_y + (size_t)(c * CHUNKS + i) * QDIM + (size_t)h * HD + tc * 8;
#pragma unroll
        for (int jj = 0; jj < 8; jj++) {
            sY[i * 129 + tc * 8 + jj] = acc[ii][jj] + yin[jj];
        }
    }
    __syncthreads();

    if (tid < 128) {
        float s = 0.f;
#pragma unroll 4
        for (int e = 0; e < 128; e++) {
            float t = sY[tid * 129 + e];
            s += t * t;
        }
        sScale[tid] = rsqrtf(s * (1.0f / 128.0f) + 1e-5f);
    }
    __syncthreads();

    for (int idx = tid; idx < 128 * 128; idx += 256) {
        const int i = idx >> 7, e = idx & 127;
        const size_t off = (size_t)(c * CHUNKS + i) * QDIM + (size_t)h * HD + e;
        const float gv = g_gate[off];
        const float sig = 1.f / (1.f + expf(-gv));
        g_y[off] = sY[i * 129 + e] * sScale[i] * sGn[e] * gv * sig;
    }
}

// ---------------- launch ----------------
extern "C" void kernel_launch(void* const* d_in, const int* in_sizes, int n_in,
                              void* d_out, int out_size) {
    const float* hs      = (const float*)d_in[0];
    const float* Wq      = (const float*)d_in[1];
    const float* Wk      = (const float*)d_in[2];
    const float* Wv      = (const float*)d_in[3];
    const float* Wo      = (const float*)d_in[4];
    const float* Wg      = (const float*)d_in[5];
    const float* Win     = (const float*)d_in[6];
    const float* dt_bias = (const float*)d_in[7];
    const float* A_log   = (const float*)d_in[8];
    const float* gnorm   = (const float*)d_in[9];
    float* out = (float*)d_out;

    float *q, *k, *v, *gate, *y;
    cudaGetSymbolAddress((void**)&q, g_q);
    cudaGetSymbolAddress((void**)&k, g_k);
    cudaGetSymbolAddress((void**)&v, g_v);
    cudaGetSymbolAddress((void**)&gate, g_gate);
    cudaGetSymbolAddress((void**)&y, g_y);

    const int SMEM_BIG = (128 * 129 + 2 * 16 * 128) * (int)sizeof(float);
    cudaFuncSetAttribute(intra_kernel, cudaFuncAttributeMaxDynamicSharedMemorySize, SMEM_BIG);
    cudaFuncSetAttribute(inter_kernel, cudaFuncAttributeMaxDynamicSharedMemorySize, SMEM_BIG);
    const int SMEM_GEMM = 2 * 12288 * (int)sizeof(unsigned);    // 96KB
    cudaFuncSetAttribute(gemm_big, cudaFuncAttributeMaxDynamicSharedMemorySize, SMEM_GEMM);
    cudaFuncSetAttribute(gemm_qkvg, cudaFuncAttributeMaxDynamicSharedMemorySize, SMEM_GEMM);

    // fused Q/K/V/G projections: one launch, 40 x-tiles x 32 m-tiles = 1280 CTAs
    gemm_qkvg<<<dim3(40, LSEQ / 128), 512, SMEM_GEMM>>>(hs, Wq, Wk, Wv, Wg, q, k, v, gate);
    dt_kernel<<<LSEQ, 256>>>(hs, Win, dt_bias);
    scan_kernel<<<NC * NH, 32>>>(A_log);

    // rope
    {
        long tq = (long)LSEQ * NH * 64;
        rope_kernel<<<(unsigned)((tq + 255) / 256), 256>>>(q, NH);
        long tk = (long)LSEQ * NKV * 64;
        rope_kernel<<<(unsigned)((tk + 255) / 256), 256>>>(k, NKV);
    }

    // attention (round-10 FFMA versions)
    intra_kernel<<<dim3(NC, NH), 256, SMEM_BIG>>>();
    recur_kernel<<<(NH * HD * HD + 1023) / 1024, 1024>>>();
    inter_kernel<<<dim3(NC, NH), 256, SMEM_BIG>>>(gnorm);

    // output projection
    gemm_big<<<dim3(HIDDEN / 256, LSEQ / 128), 512, SMEM_GEMM>>>(y, Wo, out, LSEQ, HIDDEN, QDIM);
}

// round 14
// speedup vs baseline: 1.2621x; 1.2621x over previous
#include <cuda_runtime.h>
#include <cuda_bf16.h>
#include <math.h>
#include <stdint.h>

#define LSEQ   4096
#define HIDDEN 4096
#define NH     32
#define NKV    8
#define HD     128
#define CHUNKS 128
#define NC     32
#define QDIM   4096   // NH*HD
#define KVDIM  1024   // NKV*HD

// single dynamic smem declaration for ALL kernels
extern __shared__ __align__(1024) unsigned char dyn_smem[];

// ---------------- scratch (static device globals; no allocation) ----------------
__device__ float g_q[(size_t)LSEQ * QDIM];
__device__ float g_k[(size_t)LSEQ * KVDIM];
__device__ float g_v[(size_t)LSEQ * KVDIM];
__device__ float g_gate[(size_t)LSEQ * QDIM];
__device__ float g_y[(size_t)LSEQ * QDIM];
__device__ float g_dt[LSEQ * NH];
__device__ float g_G[LSEQ * NH];
__device__ float g_cdec[NC * NH];
__device__ float g_cs[(size_t)NC * NH * HD * HD];
__device__ float g_prev[(size_t)NC * NH * HD * HD];

__device__ __forceinline__ unsigned pack_bf2(float a, float b) {
    __nv_bfloat162 t = __floats2bfloat162_rn(a, b);
    return reinterpret_cast<unsigned&>(t);
}

// ---------------- bf16x3 tensor-core GEMM, 128x256 CTA / 512 threads (round-10 winner) ----
__global__ void __launch_bounds__(512, 1) gemm_big(const float* __restrict__ A,
                                                   const float* __restrict__ B,
                                                   float* __restrict__ C,
                                                   int M, int N, int K) {
    unsigned* smem_u = (unsigned*)dyn_smem;
    const int tid = threadIdx.x;
    const int warp = tid >> 5, lane = tid & 31;
    const int wm = warp >> 3, wn = warp & 7;   // 2 x 8 warps, warp tile 64x32
    const int bm = blockIdx.y * 128, bn = blockIdx.x * 256;

    float acc[4][4][4];
#pragma unroll
    for (int a = 0; a < 4; a++)
#pragma unroll
        for (int b = 0; b < 4; b++)
#pragma unroll
            for (int c = 0; c < 4; c++) acc[a][b][c] = 0.f;

    const int c4 = tid & 7;
    const int k0 = c4 * 4;
    const int ks0 = c4 >> 2;
    const int ki = (c4 & 3) * 4;
    const int row0 = tid >> 3;            // 0..63

    const float* a_base = A + (size_t)(bm + row0) * K + k0;
    const float* b_base = B + (size_t)(bn + row0) * K + k0;
    const size_t gstride = (size_t)64 * K;

    const int riA = row0 & 15, tmA = row0 >> 4;
    const int laneA = (riA & 7) * 4 + ((ki & 7) >> 1);
    const int regA = (riA >> 3) + ((ki >> 3) << 1);
    const int a_st0 = ((ks0 * 8 + tmA) * 32 + laneA) * 4 + regA;
    const int tnB = row0 >> 3, ciB = row0 & 7;
    const int laneB = ciB * 4 + ((ki & 7) >> 1);
    const int regB = ki >> 3;
    const int b_st0 = ((ks0 * 32 + tnB) * 32 + laneB) * 2 + regB;

    float4 ar[2], br[4];
#pragma unroll
    for (int i = 0; i < 2; i++) ar[i] = *(const float4*)(a_base + i * gstride);
#pragma unroll
    for (int i = 0; i < 4; i++) br[i] = *(const float4*)(b_base + i * gstride);

    auto store_tiles = [&](unsigned* base) {
        unsigned* Ah = base;
        unsigned* Al = base + 2048;
        unsigned* Bh = base + 4096;
        unsigned* Bl = base + 8192;
#pragma unroll
        for (int i = 0; i < 2; i++) {
            float4 v = ar[i];
            __nv_bfloat162 h01 = __floats2bfloat162_rn(v.x, v.y);
            __nv_bfloat162 h23 = __floats2bfloat162_rn(v.z, v.w);
            float2 f01 = __bfloat1622float2(h01);
            float2 f23 = __bfloat1622float2(h23);
            const int st = a_st0 + i * 512;
            Ah[st]     = reinterpret_cast<unsigned&>(h01);
            Ah[st + 4] = reinterpret_cast<unsigned&>(h23);
            Al[st]     = pack_bf2(v.x - f01.x, v.y - f01.y);
            Al[st + 4] = pack_bf2(v.z - f23.x, v.w - f23.y);
        }
#pragma unroll
        for (int i = 0; i < 4; i++) {
            float4 v = br[i];
            __nv_bfloat162 h01 = __floats2bfloat162_rn(v.x, v.y);
            __nv_bfloat162 h23 = __floats2bfloat162_rn(v.z, v.w);
            float2 f01 = __bfloat1622float2(h01);
            float2 f23 = __bfloat1622float2(h23);
            const int st = b_st0 + i * 512;
            Bh[st]     = reinterpret_cast<unsigned&>(h01);
            Bh[st + 2] = reinterpret_cast<unsigned&>(h23);
            Bl[st]     = pack_bf2(v.x - f01.x, v.y - f01.y);
            Bl[st + 2] = pack_bf2(v.z - f23.x, v.w - f23.y);
        }
    };

    store_tiles(smem_u);
    __syncthreads();

    const int nk = K >> 5;
    for (int kb = 0; kb < nk; kb++) {
        const int cur = kb & 1;
        const bool has_next = (kb + 1) < nk;
        if (has_next) {
            const int off = (kb + 1) * 32;
#pragma unroll
            for (int i = 0; i < 2; i++) ar[i] = *(const float4*)(a_base + i * gstride + off);
#pragma unroll
            for (int i = 0; i < 4; i++) br[i] = *(const float4*)(b_base + i * gstride + off);
        }
        const unsigned* base = smem_u + cur * 12288;
        const unsigned* Ahb = base;
        const unsigned* Alb = base + 2048;
        const unsigned* Bhb = base + 4096;
        const unsigned* Blb = base + 8192;
#pragma unroll
        for (int ks = 0; ks < 2; ks++) {
            unsigned bh[4][2], bl[4][2];
#pragma unroll
            for (int nt = 0; nt < 4; nt++) {
                const int tn = wn * 4 + nt;
                uint2 vh = *(const uint2*)(Bhb + ((ks * 32 + tn) * 32 + lane) * 2);
                uint2 vl = *(const uint2*)(Blb + ((ks * 32 + tn) * 32 + lane) * 2);
                bh[nt][0] = vh.x; bh[nt][1] = vh.y;
                bl[nt][0] = vl.x; bl[nt][1] = vl.y;
            }
#pragma unroll
            for (int mt = 0; mt < 4; mt++) {
                const int tm = wm * 4 + mt;
                uint4 avh = *(const uint4*)(Ahb + ((ks * 8 + tm) * 32 + lane) * 4);
                uint4 avl = *(const uint4*)(Alb + ((ks * 8 + tm) * 32 + lane) * 4);
#pragma unroll
                for (int nt = 0; nt < 4; nt++) {
                    asm volatile(
                        "mma.sync.aligned.m16n8k16.row.col.f32.bf16.bf16.f32 "
                        "{%0,%1,%2,%3}, {%4,%5,%6,%7}, {%8,%9}, {%0,%1,%2,%3};"
                        : "+f"(acc[mt][nt][0]), "+f"(acc[mt][nt][1]),
                          "+f"(acc[mt][nt][2]), "+f"(acc[mt][nt][3])
                        : "r"(avh.x), "r"(avh.y), "r"(avh.z), "r"(avh.w),
                          "r"(bh[nt][0]), "r"(bh[nt][1]));
                    asm volatile(
                        "mma.sync.aligned.m16n8k16.row.col.f32.bf16.bf16.f32 "
                        "{%0,%1,%2,%3}, {%4,%5,%6,%7}, {%8,%9}, {%0,%1,%2,%3};"
                        : "+f"(acc[mt][nt][0]), "+f"(acc[mt][nt][1]),
                          "+f"(acc[mt][nt][2]), "+f"(acc[mt][nt][3])
                        : "r"(avh.x), "r"(avh.y), "r"(avh.z), "r"(avh.w),
                          "r"(bl[nt][0]), "r"(bl[nt][1]));
                    asm volatile(
                        "mma.sync.aligned.m16n8k16.row.col.f32.bf16.bf16.f32 "
                        "{%0,%1,%2,%3}, {%4,%5,%6,%7}, {%8,%9}, {%0,%1,%2,%3};"
                        : "+f"(acc[mt][nt][0]), "+f"(acc[mt][nt][1]),
                          "+f"(acc[mt][nt][2]), "+f"(acc[mt][nt][3])
                        : "r"(avl.x), "r"(avl.y), "r"(avl.z), "r"(avl.w),
                          "r"(bh[nt][0]), "r"(bh[nt][1]));
                }
            }
        }
        if (has_next) {
            store_tiles(smem_u + ((kb + 1) & 1) * 12288);
            __syncthreads();
        }
    }

#pragma unroll
    for (int mt = 0; mt < 4; mt++) {
        const int row0e = bm + wm * 64 + mt * 16 + (lane >> 2);
#pragma unroll
        for (int nt = 0; nt < 4; nt++) {
            const int col = bn + wn * 32 + nt * 8 + (lane & 3) * 2;
            *(float2*)(C + (size_t)row0e * N + col) = make_float2(acc[mt][nt][0], acc[mt][nt][1]);
            *(float2*)(C + (size_t)(row0e + 8) * N + col) = make_float2(acc[mt][nt][2], acc[mt][nt][3]);
        }
    }
}

// ---------------- dt = softplus(hs @ Win^T + dt_bias), smem-tiled ----------------
// 256 blocks x 16 rows; k-chunks of 256. smem: hs tile 16x256 + Win tile 32x256 = 48KB.
__global__ void __launch_bounds__(256) dt_kernel(const float* __restrict__ hs,
                                                 const float* __restrict__ Win,
                                                 const float* __restrict__ dtb) {
    float* sH = (float*)dyn_smem;          // 16*256
    float* sW = sH + 16 * 256;             // 32*256
    const int tid = threadIdx.x;
    const int l0 = blockIdx.x * 16;
    const int r = tid >> 4;                // 0..15
    const int hh = tid & 15;               // 0..15 (handles hh and hh+16)

    float acc0 = 0.f, acc1 = 0.f;
    for (int kc = 0; kc < HIDDEN; kc += 256) {
        // load hs tile: 16 rows x 256 cols = 1024 float4s -> 4 per thread
#pragma unroll
        for (int j = 0; j < 4; j++) {
            const int i = tid + j * 256;           // 0..1023
            const int row = i >> 6, q4 = i & 63;
            *(float4*)(sH + row * 256 + q4 * 4) =
                *(const float4*)(hs + (size_t)(l0 + row) * HIDDEN + kc + q4 * 4);
        }
        // load Win tile: 32 rows x 256 cols = 2048 float4s -> 8 per thread
#pragma unroll
        for (int j = 0; j < 8; j++) {
            const int i = tid + j * 256;           // 0..2047
            const int row = i >> 6, q4 = i & 63;
            *(float4*)(sW + row * 256 + q4 * 4) =
                *(const float4*)(Win + (size_t)row * HIDDEN + kc + q4 * 4);
        }
        __syncthreads();
        const float* hrow = sH + r * 256;
        const float* w0 = sW + hh * 256;
        const float* w1 = sW + (hh + 16) * 256;
#pragma unroll 8
        for (int k = 0; k < 256; k++) {
            const float a = hrow[k];
            acc0 += a * w0[k];
            acc1 += a * w1[k];
        }
        __syncthreads();
    }
    {
        float t = acc0 + dtb[hh];
        g_dt[(l0 + r) * NH + hh] = fmaxf(t, 0.f) + log1pf(expf(-fabsf(t)));
        t = acc1 + dtb[hh + 16];
        g_dt[(l0 + r) * NH + hh + 16] = fmaxf(t, 0.f) + log1pf(expf(-fabsf(t)));
    }
}

// ---------------- per-(chunk,head) inclusive cumsum of g = dt*A ----------------
__global__ void scan_kernel(const float* __restrict__ A_log) {
    const int hc = blockIdx.x;
    const int h = hc & (NH - 1);
    const int c = hc >> 5;
    const float A = -expf(A_log[h]);
    const int lane = threadIdx.x;
    float carry = 0.f;
    for (int s0 = 0; s0 < CHUNKS; s0 += 32) {
        const int l = c * CHUNKS + s0 + lane;
        float val = g_dt[l * NH + h] * A;
#pragma unroll
        for (int off = 1; off < 32; off <<= 1) {
            float n = __shfl_up_sync(0xffffffffu, val, off);
            if (lane >= off) val += n;
        }
        val += carry;
        g_G[l * NH + h] = val;
        carry = __shfl_sync(0xffffffffu, val, 31);
    }
    if (lane == 31) g_cdec[c * NH + h] = expf(carry);
}

// ---------------- RoPE in place (exp2f inv-freq, no powf) ----------------
__global__ void rope_kernel(float* __restrict__ x, int nheads) {
    const long idx = (long)blockIdx.x * blockDim.x + threadIdx.x;
    const long total = (long)LSEQ * nheads * 64;
    if (idx >= total) return;
    const int d = (int)(idx & 63);
    const int h = (int)((idx >> 6) % nheads);
    const long l = idx / ((long)64 * nheads);
    // inv = 10000^(-d/64) = 2^(-d * log2(10000)/64)
    const float inv = exp2f((float)d * -0.20764136891f);  // log2(10000)/64
    const float ang = (float)l * inv;
    float cs, sn;
    __sincosf(ang, &sn, &cs);
    float* base = x + l * (size_t)(nheads * HD) + (size_t)h * HD;
    const float x1 = base[d];
    const float x2 = base[d + 64];
    base[d]      = x1 * cs - x2 * sn;
    base[d + 64] = x2 * cs + x1 * sn;
}

// ---------------- intra-chunk: scores, decay mask, y_intra, cstates (round-10 FFMA) ---
__global__ void __launch_bounds__(256) intra_kernel() {
    float* smem = (float*)dyn_smem;
    float* sP = smem;                 // 128*129, P^T (stored [j][i])
    float* sA = sP + 128 * 129;       // 16*128
    float* sB = sA + 16 * 128;        // 16*128
    __shared__ float sG[128];
    __shared__ float sDt[128];

    const int c = blockIdx.x, h = blockIdx.y;
    const int kvh = h >> 2;
    const int tid = threadIdx.x;
    const int tr = tid >> 4, tc = tid & 15;
    const float* qp = g_q + (size_t)(c * CHUNKS) * QDIM + (size_t)h * HD;
    const float* kp = g_k + (size_t)(c * CHUNKS) * KVDIM + (size_t)kvh * HD;
    const float* vp = g_v + (size_t)(c * CHUNKS) * KVDIM + (size_t)kvh * HD;

    if (tid < 128) {
        sG[tid] = g_G[(c * CHUNKS + tid) * NH + h];
        sDt[tid] = g_dt[(c * CHUNKS + tid) * NH + h];
    }
    __syncthreads();
    const float Glast = sG[127];

    float acc[8][8];
#pragma unroll
    for (int i = 0; i < 8; i++)
#pragma unroll
        for (int j = 0; j < 8; j++) acc[i][j] = 0.f;

    const int rowA = tid >> 1;
    const int kk0 = (tid & 1) * 8;
    for (int d0 = 0; d0 < HD; d0 += 16) {
        const float* ap = qp + (size_t)rowA * QDIM + d0 + kk0;
        float4 a0 = *(const float4*)ap;
        float4 a1 = *(const float4*)(ap + 4);
        sA[(kk0 + 0) * 128 + rowA] = a0.x;
        sA[(kk0 + 1) * 128 + rowA] = a0.y;
        sA[(kk0 + 2) * 128 + rowA] = a0.z;
        sA[(kk0 + 3) * 128 + rowA] = a0.w;
        sA[(kk0 + 4) * 128 + rowA] = a1.x;
        sA[(kk0 + 5) * 128 + rowA] = a1.y;
        sA[(kk0 + 6) * 128 + rowA] = a1.z;
        sA[(kk0 + 7) * 128 + rowA] = a1.w;
        const float* bp = kp + (size_t)rowA * KVDIM + d0 + kk0;
        float4 b0 = *(const float4*)bp;
        float4 b1 = *(const float4*)(bp + 4);
        sB[(kk0 + 0) * 128 + rowA] = b0.x;
        sB[(kk0 + 1) * 128 + rowA] = b0.y;
        sB[(kk0 + 2) * 128 + rowA] = b0.z;
        sB[(kk0 + 3) * 128 + rowA] = b0.w;
        sB[(kk0 + 4) * 128 + rowA] = b1.x;
        sB[(kk0 + 5) * 128 + rowA] = b1.y;
        sB[(kk0 + 6) * 128 + rowA] = b1.z;
        sB[(kk0 + 7) * 128 + rowA] = b1.w;
        __syncthreads();
#pragma unroll
        for (int kk = 0; kk < 16; kk++) {
            float av[8], bv[8];
#pragma unroll
            for (int i = 0; i < 8; i++) av[i] = sA[kk * 128 + tr * 8 + i];
#pragma unroll
            for (int j = 0; j < 8; j++) bv[j] = sB[kk * 128 + tc * 8 + j];
#pragma unroll
            for (int i = 0; i < 8; i++)
#pragma unroll
                for (int j = 0; j < 8; j++) acc[i][j] += av[i] * bv[j];
        }
        __syncthreads();
    }

#pragma unroll
    for (int ii = 0; ii < 8; ii++) {
        const int i = tr * 8 + ii;
        const float Gi = sG[i];
#pragma unroll
        for (int jj = 0; jj < 8; jj++) {
            const int j = tc * 8 + jj;
            const float p = (i >= j) ? acc[ii][jj] * expf(Gi - sG[j]) : 0.f;
            sP[j * 129 + i] = p;
        }
    }
    __syncthreads();

#pragma unroll
    for (int i = 0; i < 8; i++)
#pragma unroll
        for (int j = 0; j < 8; j++) acc[i][j] = 0.f;
    {
        const int kkl = tid >> 4;
        const int e0 = (tid & 15) * 8;
        for (int j0 = 0; j0 < 128; j0 += 16) {
            const float dtv = sDt[j0 + kkl];
            const float* xp = vp + (size_t)(j0 + kkl) * KVDIM + e0;
            float4 x0 = *(const float4*)xp;
            float4 x1 = *(const float4*)(xp + 4);
            sB[kkl * 128 + e0 + 0] = x0.x * dtv;
            sB[kkl * 128 + e0 + 1] = x0.y * dtv;
            sB[kkl * 128 + e0 + 2] = x0.z * dtv;
            sB[kkl * 128 + e0 + 3] = x0.w * dtv;
            sB[kkl * 128 + e0 + 4] = x1.x * dtv;
            sB[kkl * 128 + e0 + 5] = x1.y * dtv;
            sB[kkl * 128 + e0 + 6] = x1.z * dtv;
            sB[kkl * 128 + e0 + 7] = x1.w * dtv;
            __syncthreads();
#pragma unroll
            for (int kk = 0; kk < 16; kk++) {
                float av[8], bv[8];
#pragma unroll
                for (int i = 0; i < 8; i++) av[i] = sP[(j0 + kk) * 129 + tr * 8 + i];
#pragma unroll
                for (int j = 0; j < 8; j++) bv[j] = sB[kk * 128 + tc * 8 + j];
#pragma unroll
                for (int i = 0; i < 8; i++)
#pragma unroll
                    for (int j = 0; j < 8; j++) acc[i][j] += av[i] * bv[j];
            }
            __syncthreads();
        }
    }
#pragma unroll
    for (int ii = 0; ii < 8; ii++) {
        float* yp = g_y + (size_t)(c * CHUNKS + tr * 8 + ii) * QDIM + (size_t)h * HD + tc * 8;
        *(float4*)yp = make_float4(acc[ii][0], acc[ii][1], acc[ii][2], acc[ii][3]);
        *(float4*)(yp + 4) = make_float4(acc[ii][4], acc[ii][5], acc[ii][6], acc[ii][7]);
    }

#pragma unroll
    for (int i = 0; i < 8; i++)
#pragma unroll
        for (int j = 0; j < 8; j++) acc[i][j] = 0.f;
    {
        const int kkl = tid >> 4;
        const int e0 = (tid & 15) * 8;
        for (int j0 = 0; j0 < 128; j0 += 16) {
            const float w = expf(Glast - sG[j0 + kkl]);
            const float dtv = sDt[j0 + kkl];
            const float* kp2 = kp + (size_t)(j0 + kkl) * KVDIM + e0;
            const float* xp = vp + (size_t)(j0 + kkl) * KVDIM + e0;
            float4 k0v = *(const float4*)kp2;
            float4 k1v = *(const float4*)(kp2 + 4);
            float4 x0 = *(const float4*)xp;
            float4 x1 = *(const float4*)(xp + 4);
            sA[kkl * 128 + e0 + 0] = k0v.x * w;
            sA[kkl * 128 + e0 + 1] = k0v.y * w;
            sA[kkl * 128 + e0 + 2] = k0v.z * w;
            sA[kkl * 128 + e0 + 3] = k0v.w * w;
            sA[kkl * 128 + e0 + 4] = k1v.x * w;
            sA[kkl * 128 + e0 + 5] = k1v.y * w;
            sA[kkl * 128 + e0 + 6] = k1v.z * w;
            sA[kkl * 128 + e0 + 7] = k1v.w * w;
            sB[kkl * 128 + e0 + 0] = x0.x * dtv;
            sB[kkl * 128 + e0 + 1] = x0.y * dtv;
            sB[kkl * 128 + e0 + 2] = x0.z * dtv;
            sB[kkl * 128 + e0 + 3] = x0.w * dtv;
            sB[kkl * 128 + e0 + 4] = x1.x * dtv;
            sB[kkl * 128 + e0 + 5] = x1.y * dtv;
            sB[kkl * 128 + e0 + 6] = x1.z * dtv;
            sB[kkl * 128 + e0 + 7] = x1.w * dtv;
            __syncthreads();
#pragma unroll
            for (int kk = 0; kk < 16; kk++) {
                float av[8], bv[8];
#pragma unroll
                for (int i = 0; i < 8; i++) av[i] = sA[kk * 128 + tr * 8 + i];
#pragma unroll
                for (int j = 0; j < 8; j++) bv[j] = sB[kk * 128 + tc * 8 + j];
#pragma unroll
                for (int i = 0; i < 8; i++)
#pragma unroll
                    for (int j = 0; j < 8; j++) acc[i][j] += av[i] * bv[j];
            }
            __syncthreads();
        }
    }
    float* csp = g_cs + (size_t)(c * NH + h) * HD * HD;
#pragma unroll
    for (int ii = 0; ii < 8; ii++) {
        float* cp = csp + (size_t)(tr * 8 + ii) * HD + tc * 8;
        *(float4*)cp = make_float4(acc[ii][0], acc[ii][1], acc[ii][2], acc[ii][3]);
        *(float4*)(cp + 4) = make_float4(acc[ii][4], acc[ii][5], acc[ii][6], acc[ii][7]);
    }
}

// ---------------- sequential chunk recurrence ----------------
__global__ void recur_kernel() {
    const int idx = blockIdx.x * blockDim.x + threadIdx.x;
    if (idx >= NH * HD * HD) return;
    const int h = idx / (HD * HD);
    const int de = idx % (HD * HD);
    float state = 0.f;
#pragma unroll 1
    for (int c = 0; c < NC; c++) {
        const size_t off = (size_t)(c * NH + h) * HD * HD + de;
        g_prev[off] = state;
        state = state * g_cdec[c * NH + h] + g_cs[off];
    }
}

// ---------------- inter-chunk + combine + RMSNorm + SiLU gate (round-10 FFMA) --------
__global__ void __launch_bounds__(256) inter_kernel(const float* __restrict__ gnorm) {
    float* smem = (float*)dyn_smem;
    float* sY = smem;               // 128*129
    float* sA = sY + 128 * 129;     // 16*128
    float* sB = sA + 16 * 128;      // 16*128
    __shared__ float sG[128];
    __shared__ float sScale[128];
    __shared__ float sGn[128];

    const int c = blockIdx.x, h = blockIdx.y;
    const int tid = threadIdx.x;
    const int tr = tid >> 4, tc = tid & 15;
    const float* qp = g_q + (size_t)(c * CHUNKS) * QDIM + (size_t)h * HD;
    const float* pp = g_prev + (size_t)(c * NH + h) * HD * HD;

    if (tid < 128) {
        sG[tid] = g_G[(c * CHUNKS + tid) * NH + h];
        sGn[tid] = gnorm[tid];
    }
    __syncthreads();

    float acc[8][8];
#pragma unroll
    for (int i = 0; i < 8; i++)
#pragma unroll
        for (int j = 0; j < 8; j++) acc[i][j] = 0.f;

    const int rowA = tid >> 1;
    const int kk0 = (tid & 1) * 8;
    const int kkl = tid >> 4;
    const int e0 = (tid & 15) * 8;
    for (int d0 = 0; d0 < HD; d0 += 16) {
        const float eg = expf(sG[rowA]);
        const float* ap = qp + (size_t)rowA * QDIM + d0 + kk0;
        float4 a0 = *(const float4*)ap;
        float4 a1 = *(const float4*)(ap + 4);
        sA[(kk0 + 0) * 128 + rowA] = a0.x * eg;
        sA[(kk0 + 1) * 128 + rowA] = a0.y * eg;
        sA[(kk0 + 2) * 128 + rowA] = a0.z * eg;
        sA[(kk0 + 3) * 128 + rowA] = a0.w * eg;
        sA[(kk0 + 4) * 128 + rowA] = a1.x * eg;
        sA[(kk0 + 5) * 128 + rowA] = a1.y * eg;
        sA[(kk0 + 6) * 128 + rowA] = a1.z * eg;
        sA[(kk0 + 7) * 128 + rowA] = a1.w * eg;
        const float* bp = pp + (size_t)(d0 + kkl) * HD + e0;
        float4 b0 = *(const float4*)bp;
        float4 b1 = *(const float4*)(bp + 4);
        sB[kkl * 128 + e0 + 0] = b0.x;
        sB[kkl * 128 + e0 + 1] = b0.y;
        sB[kkl * 128 + e0 + 2] = b0.z;
        sB[kkl * 128 + e0 + 3] = b0.w;
        sB[kkl * 128 + e0 + 4] = b1.x;
        sB[kkl * 128 + e0 + 5] = b1.y;
        sB[kkl * 128 + e0 + 6] = b1.z;
        sB[kkl * 128 + e0 + 7] = b1.w;
        __syncthreads();
#pragma unroll
        for (int kk = 0; kk < 16; kk++) {
            float av[8], bv[8];
#pragma unroll
            for (int i = 0; i < 8; i++) av[i] = sA[kk * 128 + tr * 8 + i];
#pragma unroll
            for (int j = 0; j < 8; j++) bv[j] = sB[kk * 128 + tc * 8 + j];
#pragma unroll
            for (int i = 0; i < 8; i++)
#pragma unroll
                for (int j = 0; j < 8; j++) acc[i][j] += av[i] * bv[j];
        }
        __syncthreads();
    }

#pragma unroll
    for (int ii = 0; ii < 8; ii++) {
        const int i = tr * 8 + ii;
        const float* yin = g_y + (size_t)(c * CHUNKS + i) * QDIM + (size_t)h * HD + tc * 8;
#pragma unroll
        for (int jj = 0; jj < 8; jj++) {
            sY[i * 129 + tc * 8 + jj] = acc[ii][jj] + yin[jj];
        }
    }
    __syncthreads();

    if (tid < 128) {
        float s = 0.f;
#pragma unroll 4
        for (int e = 0; e < 128; e++) {
            float t = sY[tid * 129 + e];
            s += t * t;
        }
        sScale[tid] = rsqrtf(s * (1.0f / 128.0f) + 1e-5f);
    }
    __syncthreads();

    for (int idx = tid; idx < 128 * 128; idx += 256) {
        const int i = idx >> 7, e = idx & 127;
        const size_t off = (size_t)(c * CHUNKS + i) * QDIM + (size_t)h * HD + e;
        const float gv = g_gate[off];
        const float sig = 1.f / (1.f + expf(-gv));
        g_y[off] = sY[i * 129 + e] * sScale[i] * sGn[e] * gv * sig;
    }
}

// ---------------- launch ----------------
extern "C" void kernel_launch(void* const* d_in, const int* in_sizes, int n_in,
                              void* d_out, int out_size) {
    const float* hs      = (const float*)d_in[0];
    const float* Wq      = (const float*)d_in[1];
    const float* Wk      = (const float*)d_in[2];
    const float* Wv      = (const float*)d_in[3];
    const float* Wo      = (const float*)d_in[4];
    const float* Wg      = (const float*)d_in[5];
    const float* Win     = (const float*)d_in[6];
    const float* dt_bias = (const float*)d_in[7];
    const float* A_log   = (const float*)d_in[8];
    const float* gnorm   = (const float*)d_in[9];
    float* out = (float*)d_out;

    float *q, *k, *v, *gate, *y;
    cudaGetSymbolAddress((void**)&q, g_q);
    cudaGetSymbolAddress((void**)&k, g_k);
    cudaGetSymbolAddress((void**)&v, g_v);
    cudaGetSymbolAddress((void**)&gate, g_gate);
    cudaGetSymbolAddress((void**)&y, g_y);

    const int SMEM_BIG = (128 * 129 + 2 * 16 * 128) * (int)sizeof(float);
    cudaFuncSetAttribute(intra_kernel, cudaFuncAttributeMaxDynamicSharedMemorySize, SMEM_BIG);
    cudaFuncSetAttribute(inter_kernel, cudaFuncAttributeMaxDynamicSharedMemorySize, SMEM_BIG);
    const int SMEM_GEMM = 2 * 12288 * (int)sizeof(unsigned);    // 96KB
    cudaFuncSetAttribute(gemm_big, cudaFuncAttributeMaxDynamicSharedMemorySize, SMEM_GEMM);
    const int SMEM_DT = 48 * 256 * (int)sizeof(float);          // 48KB
    cudaFuncSetAttribute(dt_kernel, cudaFuncAttributeMaxDynamicSharedMemorySize, SMEM_DT);

    // projections (round-10 GEMM, separate launches)
    gemm_big<<<dim3(QDIM / 256, LSEQ / 128), 512, SMEM_GEMM>>>(hs, Wq, q, LSEQ, QDIM, HIDDEN);
    gemm_big<<<dim3(KVDIM / 256, LSEQ / 128), 512, SMEM_GEMM>>>(hs, Wk, k, LSEQ, KVDIM, HIDDEN);
    gemm_big<<<dim3(KVDIM / 256, LSEQ / 128), 512, SMEM_GEMM>>>(hs, Wv, v, LSEQ, KVDIM, HIDDEN);
    gemm_big<<<dim3(QDIM / 256, LSEQ / 128), 512, SMEM_GEMM>>>(hs, Wg, gate, LSEQ, QDIM, HIDDEN);
    dt_kernel<<<LSEQ / 16, 256, SMEM_DT>>>(hs, Win, dt_bias);
    scan_kernel<<<NC * NH, 32>>>(A_log);

    // rope
    {
        long tq = (long)LSEQ * NH * 64;
        rope_kernel<<<(unsigned)((tq + 255) / 256), 256>>>(q, NH);
        long tk = (long)LSEQ * NKV * 64;
        rope_kernel<<<(unsigned)((tk + 255) / 256), 256>>>(k, NKV);
    }

    // attention (round-10 FFMA versions)
    intra_kernel<<<dim3(NC, NH), 256, SMEM_BIG>>>();
    recur_kernel<<<(NH * HD * HD + 1023) / 1024, 1024>>>();
    inter_kernel<<<dim3(NC, NH), 256, SMEM_BIG>>>(gnorm);

    // output projection
    gemm_big<<<dim3(HIDDEN / 256, LSEQ / 128), 512, SMEM_GEMM>>>(y, Wo, out, LSEQ, HIDDEN, QDIM);
}

// round 15
// speedup vs baseline: 1.3350x; 1.0578x over previous
#include <cuda_runtime.h>
#include <cuda_bf16.h>
#include <math.h>
#include <stdint.h>

#define LSEQ   4096
#define HIDDEN 4096
#define NH     32
#define NKV    8
#define HD     128
#define CHUNKS 128
#define NC     32
#define QDIM   4096   // NH*HD
#define KVDIM  1024   // NKV*HD

// single dynamic smem declaration for ALL kernels
extern __shared__ __align__(1024) unsigned char dyn_smem[];

// ---------------- scratch (static device globals; no allocation) ----------------
__device__ float g_q[(size_t)LSEQ * QDIM];
__device__ float g_k[(size_t)LSEQ * KVDIM];
__device__ float g_v[(size_t)LSEQ * KVDIM];
__device__ float g_gate[(size_t)LSEQ * QDIM];
__device__ float g_y[(size_t)LSEQ * QDIM];
__device__ float g_part[(size_t)LSEQ * QDIM];   // split-K partial
__device__ float g_dt[LSEQ * NH];
__device__ float g_G[LSEQ * NH];
__device__ float g_cdec[NC * NH];
__device__ float g_cs[(size_t)NC * NH * HD * HD];
__device__ float g_prev[(size_t)NC * NH * HD * HD];

__device__ __forceinline__ unsigned pack_bf2(float a, float b) {
    __nv_bfloat162 t = __floats2bfloat162_rn(a, b);
    return reinterpret_cast<unsigned&>(t);
}

// ---------------- bf16x3 tensor-core GEMM, 128x256 CTA / 512 threads, optional split-K --
// C[M,N] = A[M,K] @ B[N,K]^T, fp32 acc, MMAs hh+hl+lh.
// splitK==1: grid.x = N/256, writes C0 over full K.
// splitK==2: grid.x = 2*(N/256); x-half 0 -> C0 with K[0,K/2), half 1 -> C1 with K[K/2,K).
__global__ void __launch_bounds__(512, 1) gemm_big(const float* __restrict__ A,
                                                   const float* __restrict__ B,
                                                   float* __restrict__ C0,
                                                   float* __restrict__ C1,
                                                   int N, int K, int splitK) {
    unsigned* smem_u = (unsigned*)dyn_smem;
    const int nx = N >> 8;
    const int half = (splitK == 2 && blockIdx.x >= nx) ? 1 : 0;
    const int kLen = K / splitK;
    const int kOff = half * kLen;
    float* C = half ? C1 : C0;

    const int tid = threadIdx.x;
    const int warp = tid >> 5, lane = tid & 31;
    const int wm = warp >> 3, wn = warp & 7;   // 2 x 8 warps, warp tile 64x32
    const int bm = blockIdx.y * 128;
    const int bn = (half ? (blockIdx.x - nx) : blockIdx.x) * 256;

    float acc[4][4][4];
#pragma unroll
    for (int a = 0; a < 4; a++)
#pragma unroll
        for (int b = 0; b < 4; b++)
#pragma unroll
            for (int c = 0; c < 4; c++) acc[a][b][c] = 0.f;

    const int c4 = tid & 7;
    const int k0 = c4 * 4;
    const int ks0 = c4 >> 2;
    const int ki = (c4 & 3) * 4;
    const int row0 = tid >> 3;            // 0..63

    const float* a_base = A + (size_t)(bm + row0) * K + kOff + k0;
    const float* b_base = B + (size_t)(bn + row0) * K + kOff + k0;
    const size_t gstride = (size_t)64 * K;

    const int riA = row0 & 15, tmA = row0 >> 4;
    const int laneA = (riA & 7) * 4 + ((ki & 7) >> 1);
    const int regA = (riA >> 3) + ((ki >> 3) << 1);
    const int a_st0 = ((ks0 * 8 + tmA) * 32 + laneA) * 4 + regA;
    const int tnB = row0 >> 3, ciB = row0 & 7;
    const int laneB = ciB * 4 + ((ki & 7) >> 1);
    const int regB = ki >> 3;
    const int b_st0 = ((ks0 * 32 + tnB) * 32 + laneB) * 2 + regB;

    float4 ar[2], br[4];
#pragma unroll
    for (int i = 0; i < 2; i++) ar[i] = *(const float4*)(a_base + i * gstride);
#pragma unroll
    for (int i = 0; i < 4; i++) br[i] = *(const float4*)(b_base + i * gstride);

    auto store_tiles = [&](unsigned* base) {
        unsigned* Ah = base;
        unsigned* Al = base + 2048;
        unsigned* Bh = base + 4096;
        unsigned* Bl = base + 8192;
#pragma unroll
        for (int i = 0; i < 2; i++) {
            float4 v = ar[i];
            __nv_bfloat162 h01 = __floats2bfloat162_rn(v.x, v.y);
            __nv_bfloat162 h23 = __floats2bfloat162_rn(v.z, v.w);
            float2 f01 = __bfloat1622float2(h01);
            float2 f23 = __bfloat1622float2(h23);
            const int st = a_st0 + i * 512;
            Ah[st]     = reinterpret_cast<unsigned&>(h01);
            Ah[st + 4] = reinterpret_cast<unsigned&>(h23);
            Al[st]     = pack_bf2(v.x - f01.x, v.y - f01.y);
            Al[st + 4] = pack_bf2(v.z - f23.x, v.w - f23.y);
        }
#pragma unroll
        for (int i = 0; i < 4; i++) {
            float4 v = br[i];
            __nv_bfloat162 h01 = __floats2bfloat162_rn(v.x, v.y);
            __nv_bfloat162 h23 = __floats2bfloat162_rn(v.z, v.w);
            float2 f01 = __bfloat1622float2(h01);
            float2 f23 = __bfloat1622float2(h23);
            const int st = b_st0 + i * 512;
            Bh[st]     = reinterpret_cast<unsigned&>(h01);
            Bh[st + 2] = reinterpret_cast<unsigned&>(h23);
            Bl[st]     = pack_bf2(v.x - f01.x, v.y - f01.y);
            Bl[st + 2] = pack_bf2(v.z - f23.x, v.w - f23.y);
        }
    };

    store_tiles(smem_u);
    __syncthreads();

    const int nk = kLen >> 5;
    for (int kb = 0; kb < nk; kb++) {
        const int cur = kb & 1;
        const bool has_next = (kb + 1) < nk;
        if (has_next) {
            const int off = (kb + 1) * 32;
#pragma unroll
            for (int i = 0; i < 2; i++) ar[i] = *(const float4*)(a_base + i * gstride + off);
#pragma unroll
            for (int i = 0; i < 4; i++) br[i] = *(const float4*)(b_base + i * gstride + off);
        }
        const unsigned* base = smem_u + cur * 12288;
        const unsigned* Ahb = base;
        const unsigned* Alb = base + 2048;
        const unsigned* Bhb = base + 4096;
        const unsigned* Blb = base + 8192;
#pragma unroll
        for (int ks = 0; ks < 2; ks++) {
            unsigned bh[4][2], bl[4][2];
#pragma unroll
            for (int nt = 0; nt < 4; nt++) {
                const int tn = wn * 4 + nt;
                uint2 vh = *(const uint2*)(Bhb + ((ks * 32 + tn) * 32 + lane) * 2);
                uint2 vl = *(const uint2*)(Blb + ((ks * 32 + tn) * 32 + lane) * 2);
                bh[nt][0] = vh.x; bh[nt][1] = vh.y;
                bl[nt][0] = vl.x; bl[nt][1] = vl.y;
            }
#pragma unroll
            for (int mt = 0; mt < 4; mt++) {
                const int tm = wm * 4 + mt;
                uint4 avh = *(const uint4*)(Ahb + ((ks * 8 + tm) * 32 + lane) * 4);
                uint4 avl = *(const uint4*)(Alb + ((ks * 8 + tm) * 32 + lane) * 4);
#pragma unroll
                for (int nt = 0; nt < 4; nt++) {
                    asm volatile(
                        "mma.sync.aligned.m16n8k16.row.col.f32.bf16.bf16.f32 "
                        "{%0,%1,%2,%3}, {%4,%5,%6,%7}, {%8,%9}, {%0,%1,%2,%3};"
                        : "+f"(acc[mt][nt][0]), "+f"(acc[mt][nt][1]),
                          "+f"(acc[mt][nt][2]), "+f"(acc[mt][nt][3])
                        : "r"(avh.x), "r"(avh.y), "r"(avh.z), "r"(avh.w),
                          "r"(bh[nt][0]), "r"(bh[nt][1]));
                    asm volatile(
                        "mma.sync.aligned.m16n8k16.row.col.f32.bf16.bf16.f32 "
                        "{%0,%1,%2,%3}, {%4,%5,%6,%7}, {%8,%9}, {%0,%1,%2,%3};"
                        : "+f"(acc[mt][nt][0]), "+f"(acc[mt][nt][1]),
                          "+f"(acc[mt][nt][2]), "+f"(acc[mt][nt][3])
                        : "r"(avh.x), "r"(avh.y), "r"(avh.z), "r"(avh.w),
                          "r"(bl[nt][0]), "r"(bl[nt][1]));
                    asm volatile(
                        "mma.sync.aligned.m16n8k16.row.col.f32.bf16.bf16.f32 "
                        "{%0,%1,%2,%3}, {%4,%5,%6,%7}, {%8,%9}, {%0,%1,%2,%3};"
                        : "+f"(acc[mt][nt][0]), "+f"(acc[mt][nt][1]),
                          "+f"(acc[mt][nt][2]), "+f"(acc[mt][nt][3])
                        : "r"(avl.x), "r"(avl.y), "r"(avl.z), "r"(avl.w),
                          "r"(bh[nt][0]), "r"(bh[nt][1]));
                }
            }
        }
        if (has_next) {
            store_tiles(smem_u + ((kb + 1) & 1) * 12288);
            __syncthreads();
        }
    }

#pragma unroll
    for (int mt = 0; mt < 4; mt++) {
        const int row0e = bm + wm * 64 + mt * 16 + (lane >> 2);
#pragma unroll
        for (int nt = 0; nt < 4; nt++) {
            const int col = bn + wn * 32 + nt * 8 + (lane & 3) * 2;
            *(float2*)(C + (size_t)row0e * N + col) = make_float2(acc[mt][nt][0], acc[mt][nt][1]);
            *(float2*)(C + (size_t)(row0e + 8) * N + col) = make_float2(acc[mt][nt][2], acc[mt][nt][3]);
        }
    }
}

// ---------------- dst += src (split-K reduction) ----------------
__global__ void add_kernel(float* __restrict__ dst, const float* __restrict__ src, int n4) {
    int i = blockIdx.x * blockDim.x + threadIdx.x;
    if (i >= n4) return;
    float4 d = ((const float4*)dst)[i];
    float4 s = ((const float4*)src)[i];
    d.x += s.x; d.y += s.y; d.z += s.z; d.w += s.w;
    ((float4*)dst)[i] = d;
}

// ---------------- dt = softplus(hs @ Win^T + dt_bias), smem-tiled ----------------
__global__ void __launch_bounds__(256) dt_kernel(const float* __restrict__ hs,
                                                 const float* __restrict__ Win,
                                                 const float* __restrict__ dtb) {
    float* sH = (float*)dyn_smem;          // 16*256
    float* sW = sH + 16 * 256;             // 32*256
    const int tid = threadIdx.x;
    const int l0 = blockIdx.x * 16;
    const int r = tid >> 4;                // 0..15
    const int hh = tid & 15;               // 0..15 (handles hh and hh+16)

    float acc0 = 0.f, acc1 = 0.f;
    for (int kc = 0; kc < HIDDEN; kc += 256) {
#pragma unroll
        for (int j = 0; j < 4; j++) {
            const int i = tid + j * 256;
            const int row = i >> 6, q4 = i & 63;
            *(float4*)(sH + row * 256 + q4 * 4) =
                *(const float4*)(hs + (size_t)(l0 + row) * HIDDEN + kc + q4 * 4);
        }
#pragma unroll
        for (int j = 0; j < 8; j++) {
            const int i = tid + j * 256;
            const int row = i >> 6, q4 = i & 63;
            *(float4*)(sW + row * 256 + q4 * 4) =
                *(const float4*)(Win + (size_t)row * HIDDEN + kc + q4 * 4);
        }
        __syncthreads();
        const float* hrow = sH + r * 256;
        const float* w0 = sW + hh * 256;
        const float* w1 = sW + (hh + 16) * 256;
#pragma unroll 8
        for (int k = 0; k < 256; k++) {
            const float a = hrow[k];
            acc0 += a * w0[k];
            acc1 += a * w1[k];
        }
        __syncthreads();
    }
    {
        float t = acc0 + dtb[hh];
        g_dt[(l0 + r) * NH + hh] = fmaxf(t, 0.f) + log1pf(expf(-fabsf(t)));
        t = acc1 + dtb[hh + 16];
        g_dt[(l0 + r) * NH + hh + 16] = fmaxf(t, 0.f) + log1pf(expf(-fabsf(t)));
    }
}

// ---------------- per-(chunk,head) inclusive cumsum of g = dt*A ----------------
__global__ void scan_kernel(const float* __restrict__ A_log) {
    const int hc = blockIdx.x;
    const int h = hc & (NH - 1);
    const int c = hc >> 5;
    const float A = -expf(A_log[h]);
    const int lane = threadIdx.x;
    float carry = 0.f;
    for (int s0 = 0; s0 < CHUNKS; s0 += 32) {
        const int l = c * CHUNKS + s0 + lane;
        float val = g_dt[l * NH + h] * A;
#pragma unroll
        for (int off = 1; off < 32; off <<= 1) {
            float n = __shfl_up_sync(0xffffffffu, val, off);
            if (lane >= off) val += n;
        }
        val += carry;
        g_G[l * NH + h] = val;
        carry = __shfl_sync(0xffffffffu, val, 31);
    }
    if (lane == 31) g_cdec[c * NH + h] = expf(carry);
}

// ---------------- RoPE in place (exp2f inv-freq) ----------------
__global__ void rope_kernel(float* __restrict__ x, int nheads) {
    const long idx = (long)blockIdx.x * blockDim.x + threadIdx.x;
    const long total = (long)LSEQ * nheads * 64;
    if (idx >= total) return;
    const int d = (int)(idx & 63);
    const int h = (int)((idx >> 6) % nheads);
    const long l = idx / ((long)64 * nheads);
    const float inv = exp2f((float)d * -0.20764136891f);  // log2(10000)/64
    const float ang = (float)l * inv;
    float cs, sn;
    __sincosf(ang, &sn, &cs);
    float* base = x + l * (size_t)(nheads * HD) + (size_t)h * HD;
    const float x1 = base[d];
    const float x2 = base[d + 64];
    base[d]      = x1 * cs - x2 * sn;
    base[d + 64] = x2 * cs + x1 * sn;
}

// ---------------- intra-chunk: scores, decay mask, y_intra, cstates (round-10 FFMA) ---
__global__ void __launch_bounds__(256) intra_kernel() {
    float* smem = (float*)dyn_smem;
    float* sP = smem;                 // 128*129, P^T (stored [j][i])
    float* sA = sP + 128 * 129;       // 16*128
    float* sB = sA + 16 * 128;        // 16*128
    __shared__ float sG[128];
    __shared__ float sDt[128];

    const int c = blockIdx.x, h = blockIdx.y;
    const int kvh = h >> 2;
    const int tid = threadIdx.x;
    const int tr = tid >> 4, tc = tid & 15;
    const float* qp = g_q + (size_t)(c * CHUNKS) * QDIM + (size_t)h * HD;
    const float* kp = g_k + (size_t)(c * CHUNKS) * KVDIM + (size_t)kvh * HD;
    const float* vp = g_v + (size_t)(c * CHUNKS) * KVDIM + (size_t)kvh * HD;

    if (tid < 128) {
        sG[tid] = g_G[(c * CHUNKS + tid) * NH + h];
        sDt[tid] = g_dt[(c * CHUNKS + tid) * NH + h];
    }
    __syncthreads();
    const float Glast = sG[127];

    float acc[8][8];
#pragma unroll
    for (int i = 0; i < 8; i++)
#pragma unroll
        for (int j = 0; j < 8; j++) acc[i][j] = 0.f;

    const int rowA = tid >> 1;
    const int kk0 = (tid & 1) * 8;
    for (int d0 = 0; d0 < HD; d0 += 16) {
        const float* ap = qp + (size_t)rowA * QDIM + d0 + kk0;
        float4 a0 = *(const float4*)ap;
        float4 a1 = *(const float4*)(ap + 4);
        sA[(kk0 + 0) * 128 + rowA] = a0.x;
        sA[(kk0 + 1) * 128 + rowA] = a0.y;
        sA[(kk0 + 2) * 128 + rowA] = a0.z;
        sA[(kk0 + 3) * 128 + rowA] = a0.w;
        sA[(kk0 + 4) * 128 + rowA] = a1.x;
        sA[(kk0 + 5) * 128 + rowA] = a1.y;
        sA[(kk0 + 6) * 128 + rowA] = a1.z;
        sA[(kk0 + 7) * 128 + rowA] = a1.w;
        const float* bp = kp + (size_t)rowA * KVDIM + d0 + kk0;
        float4 b0 = *(const float4*)bp;
        float4 b1 = *(const float4*)(bp + 4);
        sB[(kk0 + 0) * 128 + rowA] = b0.x;
        sB[(kk0 + 1) * 128 + rowA] = b0.y;
        sB[(kk0 + 2) * 128 + rowA] = b0.z;
        sB[(kk0 + 3) * 128 + rowA] = b0.w;
        sB[(kk0 + 4) * 128 + rowA] = b1.x;
        sB[(kk0 + 5) * 128 + rowA] = b1.y;
        sB[(kk0 + 6) * 128 + rowA] = b1.z;
        sB[(kk0 + 7) * 128 + rowA] = b1.w;
        __syncthreads();
#pragma unroll
        for (int kk = 0; kk < 16; kk++) {
            float av[8], bv[8];
#pragma unroll
            for (int i = 0; i < 8; i++) av[i] = sA[kk * 128 + tr * 8 + i];
#pragma unroll
            for (int j = 0; j < 8; j++) bv[j] = sB[kk * 128 + tc * 8 + j];
#pragma unroll
            for (int i = 0; i < 8; i++)
#pragma unroll
                for (int j = 0; j < 8; j++) acc[i][j] += av[i] * bv[j];
        }
        __syncthreads();
    }

#pragma unroll
    for (int ii = 0; ii < 8; ii++) {
        const int i = tr * 8 + ii;
        const float Gi = sG[i];
#pragma unroll
        for (int jj = 0; jj < 8; jj++) {
            const int j = tc * 8 + jj;
            const float p = (i >= j) ? acc[ii][jj] * expf(Gi - sG[j]) : 0.f;
            sP[j * 129 + i] = p;
        }
    }
    __syncthreads();

#pragma unroll
    for (int i = 0; i < 8; i++)
#pragma unroll
        for (int j = 0; j < 8; j++) acc[i][j] = 0.f;
    {
        const int kkl = tid >> 4;
        const int e0 = (tid & 15) * 8;
        for (int j0 = 0; j0 < 128; j0 += 16) {
            const float dtv = sDt[j0 + kkl];
            const float* xp = vp + (size_t)(j0 + kkl) * KVDIM + e0;
            float4 x0 = *(const float4*)xp;
            float4 x1 = *(const float4*)(xp + 4);
            sB[kkl * 128 + e0 + 0] = x0.x * dtv;
            sB[kkl * 128 + e0 + 1] = x0.y * dtv;
            sB[kkl * 128 + e0 + 2] = x0.z * dtv;
            sB[kkl * 128 + e0 + 3] = x0.w * dtv;
            sB[kkl * 128 + e0 + 4] = x1.x * dtv;
            sB[kkl * 128 + e0 + 5] = x1.y * dtv;
            sB[kkl * 128 + e0 + 6] = x1.z * dtv;
            sB[kkl * 128 + e0 + 7] = x1.w * dtv;
            __syncthreads();
#pragma unroll
            for (int kk = 0; kk < 16; kk++) {
                float av[8], bv[8];
#pragma unroll
                for (int i = 0; i < 8; i++) av[i] = sP[(j0 + kk) * 129 + tr * 8 + i];
#pragma unroll
                for (int j = 0; j < 8; j++) bv[j] = sB[kk * 128 + tc * 8 + j];
#pragma unroll
                for (int i = 0; i < 8; i++)
#pragma unroll
                    for (int j = 0; j < 8; j++) acc[i][j] += av[i] * bv[j];
            }
            __syncthreads();
        }
    }
#pragma unroll
    for (int ii = 0; ii < 8; ii++) {
        float* yp = g_y + (size_t)(c * CHUNKS + tr * 8 + ii) * QDIM + (size_t)h * HD + tc * 8;
        *(float4*)yp = make_float4(acc[ii][0], acc[ii][1], acc[ii][2], acc[ii][3]);
        *(float4*)(yp + 4) = make_float4(acc[ii][4], acc[ii][5], acc[ii][6], acc[ii][7]);
    }

#pragma unroll
    for (int i = 0; i < 8; i++)
#pragma unroll
        for (int j = 0; j < 8; j++) acc[i][j] = 0.f;
    {
        const int kkl = tid >> 4;
        const int e0 = (tid & 15) * 8;
        for (int j0 = 0; j0 < 128; j0 += 16) {
            const float w = expf(Glast - sG[j0 + kkl]);
            const float dtv = sDt[j0 + kkl];
            const float* kp2 = kp + (size_t)(j0 + kkl) * KVDIM + e0;
            const float* xp = vp + (size_t)(j0 + kkl) * KVDIM + e0;
            float4 k0v = *(const float4*)kp2;
            float4 k1v = *(const float4*)(kp2 + 4);
            float4 x0 = *(const float4*)xp;
            float4 x1 = *(const float4*)(xp + 4);
            sA[kkl * 128 + e0 + 0] = k0v.x * w;
            sA[kkl * 128 + e0 + 1] = k0v.y * w;
            sA[kkl * 128 + e0 + 2] = k0v.z * w;
            sA[kkl * 128 + e0 + 3] = k0v.w * w;
            sA[kkl * 128 + e0 + 4] = k1v.x * w;
            sA[kkl * 128 + e0 + 5] = k1v.y * w;
            sA[kkl * 128 + e0 + 6] = k1v.z * w;
            sA[kkl * 128 + e0 + 7] = k1v.w * w;
            sB[kkl * 128 + e0 + 0] = x0.x * dtv;
            sB[kkl * 128 + e0 + 1] = x0.y * dtv;
            sB[kkl * 128 + e0 + 2] = x0.z * dtv;
            sB[kkl * 128 + e0 + 3] = x0.w * dtv;
            sB[kkl * 128 + e0 + 4] = x1.x * dtv;
            sB[kkl * 128 + e0 + 5] = x1.y * dtv;
            sB[kkl * 128 + e0 + 6] = x1.z * dtv;
            sB[kkl * 128 + e0 + 7] = x1.w * dtv;
            __syncthreads();
#pragma unroll
            for (int kk = 0; kk < 16; kk++) {
                float av[8], bv[8];
#pragma unroll
                for (int i = 0; i < 8; i++) av[i] = sA[kk * 128 + tr * 8 + i];
#pragma unroll
                for (int j = 0; j < 8; j++) bv[j] = sB[kk * 128 + tc * 8 + j];
#pragma unroll
                for (int i = 0; i < 8; i++)
#pragma unroll
                    for (int j = 0; j < 8; j++) acc[i][j] += av[i] * bv[j];
            }
            __syncthreads();
        }
    }
    float* csp = g_cs + (size_t)(c * NH + h) * HD * HD;
#pragma unroll
    for (int ii = 0; ii < 8; ii++) {
        float* cp = csp + (size_t)(tr * 8 + ii) * HD + tc * 8;
        *(float4*)cp = make_float4(acc[ii][0], acc[ii][1], acc[ii][2], acc[ii][3]);
        *(float4*)(cp + 4) = make_float4(acc[ii][4], acc[ii][5], acc[ii][6], acc[ii][7]);
    }
}

// ---------------- sequential chunk recurrence ----------------
__global__ void recur_kernel() {
    const int idx = blockIdx.x * blockDim.x + threadIdx.x;
    if (idx >= NH * HD * HD) return;
    const int h = idx / (HD * HD);
    const int de = idx % (HD * HD);
    float state = 0.f;
#pragma unroll 1
    for (int c = 0; c < NC; c++) {
        const size_t off = (size_t)(c * NH + h) * HD * HD + de;
        g_prev[off] = state;
        state = state * g_cdec[c * NH + h] + g_cs[off];
    }
}

// ---------------- inter-chunk + combine + RMSNorm + SiLU gate (round-10 FFMA) --------
__global__ void __launch_bounds__(256) inter_kernel(const float* __restrict__ gnorm) {
    float* smem = (float*)dyn_smem;
    float* sY = smem;               // 128*129
    float* sA = sY + 128 * 129;     // 16*128
    float* sB = sA + 16 * 128;      // 16*128
    __shared__ float sG[128];
    __shared__ float sScale[128];
    __shared__ float sGn[128];

    const int c = blockIdx.x, h = blockIdx.y;
    const int tid = threadIdx.x;
    const int tr = tid >> 4, tc = tid & 15;
    const float* qp = g_q + (size_t)(c * CHUNKS) * QDIM + (size_t)h * HD;
    const float* pp = g_prev + (size_t)(c * NH + h) * HD * HD;

    if (tid < 128) {
        sG[tid] = g_G[(c * CHUNKS + tid) * NH + h];
        sGn[tid] = gnorm[tid];
    }
    __syncthreads();

    float acc[8][8];
#pragma unroll
    for (int i = 0; i < 8; i++)
#pragma unroll
        for (int j = 0; j < 8; j++) acc[i][j] = 0.f;

    const int rowA = tid >> 1;
    const int kk0 = (tid & 1) * 8;
    const int kkl = tid >> 4;
    const int e0 = (tid & 15) * 8;
    for (int d0 = 0; d0 < HD; d0 += 16) {
        const float eg = expf(sG[rowA]);
        const float* ap = qp + (size_t)rowA * QDIM + d0 + kk0;
        float4 a0 = *(const float4*)ap;
        float4 a1 = *(const float4*)(ap + 4);
        sA[(kk0 + 0) * 128 + rowA] = a0.x * eg;
        sA[(kk0 + 1) * 128 + rowA] = a0.y * eg;
        sA[(kk0 + 2) * 128 + rowA] = a0.z * eg;
        sA[(kk0 + 3) * 128 + rowA] = a0.w * eg;
        sA[(kk0 + 4) * 128 + rowA] = a1.x * eg;
        sA[(kk0 + 5) * 128 + rowA] = a1.y * eg;
        sA[(kk0 + 6) * 128 + rowA] = a1.z * eg;
        sA[(kk0 + 7) * 128 + rowA] = a1.w * eg;
        const float* bp = pp + (size_t)(d0 + kkl) * HD + e0;
        float4 b0 = *(const float4*)bp;
        float4 b1 = *(const float4*)(bp + 4);
        sB[kkl * 128 + e0 + 0] = b0.x;
        sB[kkl * 128 + e0 + 1] = b0.y;
        sB[kkl * 128 + e0 + 2] = b0.z;
        sB[kkl * 128 + e0 + 3] = b0.w;
        sB[kkl * 128 + e0 + 4] = b1.x;
        sB[kkl * 128 + e0 + 5] = b1.y;
        sB[kkl * 128 + e0 + 6] = b1.z;
        sB[kkl * 128 + e0 + 7] = b1.w;
        __syncthreads();
#pragma unroll
        for (int kk = 0; kk < 16; kk++) {
            float av[8], bv[8];
#pragma unroll
            for (int i = 0; i < 8; i++) av[i] = sA[kk * 128 + tr * 8 + i];
#pragma unroll
            for (int j = 0; j < 8; j++) bv[j] = sB[kk * 128 + tc * 8 + j];
#pragma unroll
            for (int i = 0; i < 8; i++)
#pragma unroll
                for (int j = 0; j < 8; j++) acc[i][j] += av[i] * bv[j];
        }
        __syncthreads();
    }

#pragma unroll
    for (int ii = 0; ii < 8; ii++) {
        const int i = tr * 8 + ii;
        const float* yin = g_y + (size_t)(c * CHUNKS + i) * QDIM + (size_t)h * HD + tc * 8;
#pragma unroll
        for (int jj = 0; jj < 8; jj++) {
            sY[i * 129 + tc * 8 + jj] = acc[ii][jj] + yin[jj];
        }
    }
    __syncthreads();

    if (tid < 128) {
        float s = 0.f;
#pragma unroll 4
        for (int e = 0; e < 128; e++) {
            float t = sY[tid * 129 + e];
            s += t * t;
        }
        sScale[tid] = rsqrtf(s * (1.0f / 128.0f) + 1e-5f);
    }
    __syncthreads();

    for (int idx = tid; idx < 128 * 128; idx += 256) {
        const int i = idx >> 7, e = idx & 127;
        const size_t off = (size_t)(c * CHUNKS + i) * QDIM + (size_t)h * HD + e;
        const float gv = g_gate[off];
        const float sig = 1.f / (1.f + expf(-gv));
        g_y[off] = sY[i * 129 + e] * sScale[i] * sGn[e] * gv * sig;
    }
}

// ---------------- launch ----------------
extern "C" void kernel_launch(void* const* d_in, const int* in_sizes, int n_in,
                              void* d_out, int out_size) {
    const float* hs      = (const float*)d_in[0];
    const float* Wq      = (const float*)d_in[1];
    const float* Wk      = (const float*)d_in[2];
    const float* Wv      = (const float*)d_in[3];
    const float* Wo      = (const float*)d_in[4];
    const float* Wg      = (const float*)d_in[5];
    const float* Win     = (const float*)d_in[6];
    const float* dt_bias = (const float*)d_in[7];
    const float* A_log   = (const float*)d_in[8];
    const float* gnorm   = (const float*)d_in[9];
    float* out = (float*)d_out;

    float *q, *k, *v, *gate, *y, *part;
    cudaGetSymbolAddress((void**)&q, g_q);
    cudaGetSymbolAddress((void**)&k, g_k);
    cudaGetSymbolAddress((void**)&v, g_v);
    cudaGetSymbolAddress((void**)&gate, g_gate);
    cudaGetSymbolAddress((void**)&y, g_y);
    cudaGetSymbolAddress((void**)&part, g_part);

    const int SMEM_BIG = (128 * 129 + 2 * 16 * 128) * (int)sizeof(float);
    cudaFuncSetAttribute(intra_kernel, cudaFuncAttributeMaxDynamicSharedMemorySize, SMEM_BIG);
    cudaFuncSetAttribute(inter_kernel, cudaFuncAttributeMaxDynamicSharedMemorySize, SMEM_BIG);
    const int SMEM_GEMM = 2 * 12288 * (int)sizeof(unsigned);    // 96KB
    cudaFuncSetAttribute(gemm_big, cudaFuncAttributeMaxDynamicSharedMemorySize, SMEM_GEMM);
    const int SMEM_DT = 48 * 256 * (int)sizeof(float);          // 48KB
    cudaFuncSetAttribute(dt_kernel, cudaFuncAttributeMaxDynamicSharedMemorySize, SMEM_DT);

    const int n4_big = (int)((size_t)LSEQ * QDIM / 4);

    // Q projection: split-K=2 (1024 CTAs) + reduce
    gemm_big<<<dim3(32, LSEQ / 128), 512, SMEM_GEMM>>>(hs, Wq, q, part, QDIM, HIDDEN, 2);
    add_kernel<<<(n4_big + 255) / 256, 256>>>(q, part, n4_big);
    // K, V projections: single wave each
    gemm_big<<<dim3(4, LSEQ / 128), 512, SMEM_GEMM>>>(hs, Wk, k, nullptr, KVDIM, HIDDEN, 1);
    gemm_big<<<dim3(4, LSEQ / 128), 512, SMEM_GEMM>>>(hs, Wv, v, nullptr, KVDIM, HIDDEN, 1);
    // G projection: split-K=2 + reduce
    gemm_big<<<dim3(32, LSEQ / 128), 512, SMEM_GEMM>>>(hs, Wg, gate, part, QDIM, HIDDEN, 2);
    add_kernel<<<(n4_big + 255) / 256, 256>>>(gate, part, n4_big);

    dt_kernel<<<LSEQ / 16, 256, SMEM_DT>>>(hs, Win, dt_bias);
    scan_kernel<<<NC * NH, 32>>>(A_log);

    // rope
    {
        long tq = (long)LSEQ * NH * 64;
        rope_kernel<<<(unsigned)((tq + 255) / 256), 256>>>(q, NH);
        long tk = (long)LSEQ * NKV * 64;
        rope_kernel<<<(unsigned)((tk + 255) / 256), 256>>>(k, NKV);
    }

    // attention (round-10 FFMA versions)
    intra_kernel<<<dim3(NC, NH), 256, SMEM_BIG>>>();
    recur_kernel<<<(NH * HD * HD + 1023) / 1024, 1024>>>();
    inter_kernel<<<dim3(NC, NH), 256, SMEM_BIG>>>(gnorm);

    // output projection: split-K=2 + reduce
    gemm_big<<<dim3(32, LSEQ / 128), 512, SMEM_GEMM>>>(y, Wo, out, part, HIDDEN, QDIM, 2);
    add_kernel<<<(n4_big + 255) / 256, 256>>>(out, part, n4_big);
}